// round 8
// baseline (speedup 1.0000x reference)
#include <cuda_runtime.h>
#include <cuda_bf16.h>

// LSTMStateBufferCell:
//   pos[b]  = sum_s hidden_masks[s,b]            (pos in [0,S])
//   prev    = mod(pos-1, S+1)
//   stack_X = [init_X ; X]  (index 0 = init row)
//   out_h[b,:] = stack_h[prev]*a + stack_h[pos]*(1-a),  a = |op[b]|
//   out_c[b,:] = stack_c[prev]*a + stack_c[pos]*(1-a)
// Output: f32 [2, B, H] (hidden then cell).
//
// Best-measured configuration (R5): one block per batch element, 512 threads.
//   - mask reduce: 2 strided LDGs/thread -> shfl tree -> ONE __syncthreads
//     -> each thread sums 16 warp partials (read as 4x int4 LDS.128).
//   - copy: threads 0-255 -> hidden, 256-511 -> cell; exactly one float4
//     load + one float4 store per thread (H==1024). a in {0,1} => row select;
//     general blend fallback preserved for correctness on any a.
// The timed metric is pinned at the graph-replay floor (~6.6us); this is the
// minimal-critical-path, rule-compliant kernel at that floor.

#define NTH 512

__global__ __launch_bounds__(NTH)
void lstm_state_kernel(
    const float* __restrict__ hiddens,
    const float* __restrict__ cells,
    const float* __restrict__ init_hidden,
    const float* __restrict__ init_cell,
    const int*   __restrict__ masks,
    const int*   __restrict__ op,
    float* __restrict__ out,
    int S, int B, int H)
{
    const int b   = blockIdx.x;
    const int tid = threadIdx.x;

    // Independent of the mask chain — issue first.
    const float a  = fabsf((float)__ldg(&op[b]));
    const float na = 1.0f - a;

    // ---- pos[b] = sum over the mask column ----
    int local = 0;
    for (int s = tid; s < S; s += NTH)
        local += __ldg(&masks[(size_t)s * B + b]);

    #pragma unroll
    for (int off = 16; off > 0; off >>= 1)
        local += __shfl_down_sync(0xffffffffu, local, off);

    __shared__ __align__(16) int wsum[NTH / 32];   // 16 ints
    if ((tid & 31) == 0) wsum[tid >> 5] = local;
    __syncthreads();

    // Single-stage finish: 4x LDS.128 + adds, every thread.
    int pos = 0;
    {
        const int4* w4 = (const int4*)wsum;
        #pragma unroll
        for (int k = 0; k < NTH / 128; k++) {
            int4 v = w4[k];
            pos += v.x + v.y + v.z + v.w;
        }
    }

    const int prev = (pos == 0) ? S : pos - 1;   // mod(pos-1, S+1)

    // ---- Row select / blend ----
    const size_t rowstride = (size_t)B * H;
    const int half = tid >> 8;           // 0 = hidden, 1 = cell
    const int lane = tid & 255;

    const float* data  = half ? cells     : hiddens;
    const float* initv = half ? init_cell : init_hidden;

    const float* cur_row  = (pos  == 0) ? initv
                          : data + (size_t)(pos  - 1) * rowstride + (size_t)b * H;
    const float* prev_row = (prev == 0) ? initv
                          : data + (size_t)(prev - 1) * rowstride + (size_t)b * H;
    float* dst = out + (size_t)half * rowstride + (size_t)b * H;

    if ((H & 3) == 0) {
        const int H4 = H >> 2;           // 256 for H=1024 -> exactly 1 iter/thread
        const float4* c4 = (const float4*)cur_row;
        const float4* p4 = (const float4*)prev_row;
        float4* d4 = (float4*)dst;

        if (a == 1.0f) {
            for (int i = lane; i < H4; i += 256) d4[i] = p4[i];
        } else if (a == 0.0f) {
            for (int i = lane; i < H4; i += 256) d4[i] = c4[i];
        } else {
            for (int i = lane; i < H4; i += 256) {
                float4 vp = p4[i], vc = c4[i], r;
                r.x = vp.x * a + vc.x * na;
                r.y = vp.y * a + vc.y * na;
                r.z = vp.z * a + vc.z * na;
                r.w = vp.w * a + vc.w * na;
                d4[i] = r;
            }
        }
    } else {
        for (int i = lane; i < H; i += 256)
            dst[i] = prev_row[i] * a + cur_row[i] * na;
    }
}

extern "C" void kernel_launch(void* const* d_in, const int* in_sizes, int n_in,
                              void* d_out, int out_size)
{
    const float* hiddens     = (const float*)d_in[0];
    const float* cells       = (const float*)d_in[1];
    const float* init_hidden = (const float*)d_in[2];
    const float* init_cell   = (const float*)d_in[3];
    const int*   masks       = (const int*)d_in[4];
    const int*   op          = (const int*)d_in[5];
    float*       out         = (float*)d_out;

    const int H = in_sizes[2];          // init_hidden length
    const int B = in_sizes[5];          // op length
    const int S = in_sizes[4] / B;      // masks is [S,B]

    lstm_state_kernel<<<B, NTH>>>(hiddens, cells, init_hidden, init_cell,
                                  masks, op, out, S, B, H);
}